// round 15
// baseline (speedup 1.0000x reference)
#include <cuda_runtime.h>
#include <cuda_fp16.h>
#include <cstdint>

#define K_CODES 8192
#define C_DIM   64
#define N_TOK   16384
#define HW      1024
#define TPB     256
#define MTILE   128
// stage 1 tiling
#define NTILE1  64
#define NTILES1 (K_CODES / NTILE1)   // 128
#define KSPLIT1 4
#define TPH     (NTILES1 / KSPLIT1)  // 32 tiles per K-split (even)
// stage 2 tiling
#define NTILE   64
#define NTILES  (K_CODES / NTILE)    // 128
#define NSLICE  8
#define TPSLICE (NTILES / NSLICE)    // 16
#define MARGIN2 1e-4f                // proven R5-R14

#define O_ZQST 0
#define O_IDX  1048576
#define O_ZQ   1064960
#define O_EMB  2113536
#define O_CS   2637824
#define O_AVG  2646016

// stage-1 smem: A 16KB, B 4x8KB ring, hn 8x256B ring
#define SM1_A   0
#define SM1_B   16384
#define SM1_HN  49152
#define SMEM1_TOTAL (49152 + 2048 + 128)

// stage-2 smem
#define SM_A    0
#define SM_B    32768
#define SM_HN   65536
#define SMEM2_TOTAL (65536 + 512 + 128)

typedef unsigned long long u64;
typedef unsigned int u32;

static __device__ __half g_Eh[K_CODES * C_DIM];
static __device__ __half g_Er[K_CODES * C_DIM];
static __device__ __half g_Ph[N_TOK * C_DIM];
static __device__ __half g_Pr[N_TOK * C_DIM];
static __device__ float g_hn[K_CODES];
static __device__ float g_xn2[N_TOK * 2];
static __device__ u32   g_emaxbits;
static __device__ int   g_idx[N_TOK];
static __device__ int   g_flag2[N_TOK];
static __device__ u64   g_key[N_TOK];
static __device__ int   g_list[N_TOK];
static __device__ int   g_list2[N_TOK];
static __device__ int   g_nflag;
static __device__ int   g_nflag2;
static __device__ float g_s1b1[N_TOK * KSPLIT1];
static __device__ float g_s1b2[N_TOK * KSPLIT1];
static __device__ int   g_s1i1[N_TOK * KSPLIT1];
static __device__ float g_s2b1[N_TOK * NSLICE];
static __device__ float g_s2b2[N_TOK * NSLICE];
static __device__ int   g_s2i1[N_TOK * NSLICE];
static __device__ float g_counts[K_CODES];
static __device__ float g_dw[K_CODES * C_DIM];
static __device__ float g_n;

// ---------------------------------------------------------------- helpers
__device__ __forceinline__ uint32_t smem_u32(const void* p) {
    uint32_t a;
    asm("{ .reg .u64 t; cvta.to.shared.u64 t, %1; cvt.u32.u64 %0, t; }"
        : "=r"(a) : "l"(p));
    return a;
}
__device__ __forceinline__ void cp_async16(uint32_t saddr, const void* gmem) {
    asm volatile("cp.async.cg.shared.global [%0], [%1], 16;\n" :: "r"(saddr), "l"(gmem));
}
#define CP_COMMIT() asm volatile("cp.async.commit_group;\n" ::: "memory")
#define CP_WAIT(n)  asm volatile("cp.async.wait_group %0;\n" :: "n"(n) : "memory")

__device__ __forceinline__ uint32_t sw128(uint32_t off) {
    return off ^ ((off >> 3) & 0x70);
}
__device__ __forceinline__ void ldsm4(u32& r0, u32& r1, u32& r2, u32& r3, uint32_t addr) {
    asm volatile("ldmatrix.sync.aligned.m8n8.x4.shared.b16 {%0,%1,%2,%3}, [%4];"
                 : "=r"(r0), "=r"(r1), "=r"(r2), "=r"(r3) : "r"(addr));
}
__device__ __forceinline__ void mma16816(float& d0, float& d1, float& d2, float& d3,
                                         u32 a0, u32 a1, u32 a2, u32 a3,
                                         u32 b0, u32 b1) {
    asm volatile("mma.sync.aligned.m16n8k16.row.col.f32.f16.f16.f32 "
                 "{%0,%1,%2,%3}, {%4,%5,%6,%7}, {%8,%9}, {%0,%1,%2,%3};"
                 : "+f"(d0), "+f"(d1), "+f"(d2), "+f"(d3)
                 : "r"(a0), "r"(a1), "r"(a2), "r"(a3), "r"(b0), "r"(b1));
}
__device__ __forceinline__ u32 fmono(float s) {
    u32 u = __float_as_uint(s);
    return (s < 0.0f) ? ~u : (u | 0x80000000u);
}

__device__ __forceinline__ void merge2(float& m1a, float& m2a, int& ia,
                                       float m1b, float m2b, int ib) {
    float mn = fminf(m1a, m1b);
    m2a = fmaxf(mn, fmaxf(m2a, m2b));
    ia = (m1a >= m1b) ? ia : ib;
    m1a = fmaxf(m1a, m1b);
}
__device__ __forceinline__ void t2_merge_shfl(float& b1, float& b2, int& i1, int o) {
    float ob1 = __shfl_xor_sync(0xffffffffu, b1, o);
    float ob2 = __shfl_xor_sync(0xffffffffu, b2, o);
    int   oi1 = __shfl_xor_sync(0xffffffffu, i1, o);
    if (ob1 > b1 || (ob1 == b1 && oi1 < i1)) {
        b2 = fmaxf(b1, ob2); b1 = ob1; i1 = oi1;
    } else {
        b2 = fmaxf(b2, ob1);
    }
}
__device__ __forceinline__ void tile_top2(const float acc[8][4], int v0, int v1,
                                          const float* hnp, int lq, int colbase,
                                          float& b1, float& b2, int& i1) {
    float m1[8], m2[8]; int ii[8];
    #pragma unroll
    for (int g = 0; g < 8; g++) {
        int lc = g * 8 + lq;
        float sa = acc[g][v0] - hnp[lc];
        float sb = acc[g][v1] - hnp[lc + 1];
        m1[g] = fmaxf(sa, sb);
        m2[g] = fminf(sa, sb);
        ii[g] = (sa >= sb) ? (colbase + g * 8) : (colbase + g * 8 + 1);
    }
    #pragma unroll
    for (int st = 1; st < 8; st <<= 1)
        #pragma unroll
        for (int g = 0; g < 8; g += 2 * st)
            merge2(m1[g], m2[g], ii[g], m1[g + st], m2[g + st], ii[g + st]);
    merge2(b1, b2, i1, m1[0], m2[0], ii[0]);
}

// ---------------------------------------------------------------------------
__global__ void k_initA() {
    int i = blockIdx.x * blockDim.x + threadIdx.x;
    if (i < K_CODES * C_DIM) g_dw[i] = 0.0f;
}
__global__ void k_initB() {
    int i = blockIdx.x * blockDim.x + threadIdx.x;
    if (i < K_CODES) g_counts[i] = 0.0f;
    if (i < N_TOK) g_flag2[i] = 0;
    if (i == 0) { g_nflag = 0; g_nflag2 = 0; g_n = 0.0f; g_emaxbits = 0; }
}

__global__ void k_splitE(const float* __restrict__ emb) {
    int w = (blockIdx.x * blockDim.x + threadIdx.x) >> 5;
    int lane = threadIdx.x & 31;
    if (w >= K_CODES) return;
    float s = 0.0f;
    #pragma unroll
    for (int half = 0; half < 2; half++) {
        int c = lane + half * 32;
        float x = emb[w * C_DIM + c];
        s += x * x;
        __half h = __float2half_rn(x);
        float r = x - __half2float(h);
        g_Eh[w * C_DIM + c] = h;
        g_Er[w * C_DIM + c] = __float2half_rn(r);
    }
    #pragma unroll
    for (int o = 16; o > 0; o >>= 1) s += __shfl_xor_sync(0xffffffffu, s, o);
    if (lane == 0) {
        g_hn[w] = 0.5f * s;
        atomicMax(&g_emaxbits, fmono(s));
    }
}

// ---------------------------------------------------------------------------
// STAGE 1: hh scores over one K-quarter; 2-deep software-pipelined epilogue
// (tile i's MMA overlaps tile i-1's top-2). grid (128, 4), 2 CTA/SM.
__global__ void __launch_bounds__(TPB, 2) k_dist1(const float* __restrict__ z) {
    extern __shared__ char smem[];
    const uint32_t sb = smem_u32(smem);
    const int tid = threadIdx.x;
    const int lane = tid & 31;
    const int w = tid >> 5;
    const int split = blockIdx.y;
    const int ci0 = split * TPH;

    {
        int r = tid & 127;
        int half = tid >> 7;
        int t = blockIdx.x * MTILE + r;
        const float* zp = z + (size_t)(t >> 10) * (C_DIM * HW) + (t & 1023);
        float s = 0.0f;
        #pragma unroll
        for (int j = 0; j < 32; j++) {
            int c = half * 32 + j;
            float x = zp[c * HW];
            s += x * x;
            uint32_t off = sw128((uint32_t)(r * 128 + c * 2));
            *(__half*)(smem + SM1_A + off) = __float2half_rn(x);
        }
        if (split == 0) g_xn2[t * 2 + half] = s;
    }
    __syncthreads();

    u32 afr[4][4];
    {
        int arow = w * 16 + (lane & 7) + ((lane >> 3) & 1) * 8;
        int akb  = (lane >> 4) * 16;
        #pragma unroll
        for (int q = 0; q < 4; q++) {
            uint32_t addr = sb + SM1_A + sw128((uint32_t)(arow * 128 + q * 32 + akb));
            ldsm4(afr[q][0], afr[q][1], afr[q][2], afr[q][3], addr);
        }
    }

    // B address decomposition: swizzle mask depends only on brow&7 → shared q-offsets
    const int brow = (lane & 7) + ((lane >> 4) & 1) * 8;
    const int bkb  = ((lane >> 3) & 1) * 16;
    const int lq   = 2 * (lane & 3);
    const uint32_t m = (uint32_t)((brow & 7) << 4);
    u32 bbase[4];     // per g2 group: row term + bit-4 part
    u32 qoff[4];      // per q: bits 5-6 part (shared across g2)
    #pragma unroll
    for (int g2 = 0; g2 < 4; g2++)
        bbase[g2] = sb + SM1_B + (uint32_t)((g2 * 16 + brow) * 128)
                  + ((uint32_t)bkb ^ (m & 0x10u));
    #pragma unroll
    for (int q = 0; q < 4; q++)
        qoff[q] = ((uint32_t)(q * 32)) ^ (m & 0x60u);

    auto load_tile = [&](int tile, int idx) {
        const char* src = (const char*)g_Eh + (size_t)tile * (NTILE1 * C_DIM * 2);
        uint32_t dst = sb + SM1_B + (uint32_t)(idx & 3) * 8192u;
        #pragma unroll
        for (int u = 0; u < 2; u++) {
            uint32_t off = (uint32_t)(u * TPB + tid) * 16u;
            cp_async16(dst + sw128(off), src + off);
        }
        if (tid < 16)
            cp_async16(sb + SM1_HN + (idx & 7) * 256 + tid * 16,
                       (const char*)(g_hn + tile * NTILE1) + tid * 16);
    };

    float b1_0 = -3.4e38f, b2_0 = -3.4e38f;
    float b1_1 = -3.4e38f, b2_1 = -3.4e38f;
    int i1_0 = 0, i1_1 = 0;

    float acc0[8][4], acc1[8][4];

    load_tile(ci0 + 0, 0); CP_COMMIT();
    load_tile(ci0 + 1, 1); CP_COMMIT();
    load_tile(ci0 + 2, 2); CP_COMMIT();

    // one pipelined step: compute tile 'idx' into accC, epilogue tile idx-1 from accP
    auto step = [&](int idx, float (&accC)[8][4], float (&accP)[8][4], bool do_epi) {
        if (idx + 3 <= TPH)      { CP_WAIT(2); }
        else if (idx + 2 == TPH) { CP_WAIT(1); }
        else                     { CP_WAIT(0); }
        __syncthreads();
        if (idx + 3 < TPH) { load_tile(ci0 + idx + 3, idx + 3); CP_COMMIT(); }

        #pragma unroll
        for (int g = 0; g < 8; g++)
            #pragma unroll
            for (int v = 0; v < 4; v++) accC[g][v] = 0.0f;

        const uint32_t soff = (uint32_t)(idx & 3) * 8192u;
        #pragma unroll
        for (int q = 0; q < 4; q++) {
            const uint32_t qs = qoff[q] + soff;
            u32 bfr[8][2];
            #pragma unroll
            for (int g2 = 0; g2 < 4; g2++)
                ldsm4(bfr[2 * g2][0], bfr[2 * g2][1],
                      bfr[2 * g2 + 1][0], bfr[2 * g2 + 1][1],
                      bbase[g2] + qs);
            #pragma unroll
            for (int g = 0; g < 8; g++)
                mma16816(accC[g][0], accC[g][1], accC[g][2], accC[g][3],
                         afr[q][0], afr[q][1], afr[q][2], afr[q][3],
                         bfr[g][0], bfr[g][1]);
        }

        if (do_epi) {
            const float* hnp = (const float*)(smem + SM1_HN + ((idx - 1) & 7) * 256);
            const int colbase = (ci0 + idx - 1) * NTILE1 + lq;
            tile_top2(accP, 0, 1, hnp, lq, colbase, b1_0, b2_0, i1_0);
            tile_top2(accP, 2, 3, hnp, lq, colbase, b1_1, b2_1, i1_1);
        }
    };

    #pragma unroll 1
    for (int base = 0; base < TPH; base += 2) {
        step(base,     acc0, acc1, base > 0);
        step(base + 1, acc1, acc0, true);
    }
    // final epilogue: tile TPH-1 sits in acc1
    {
        const float* hnp = (const float*)(smem + SM1_HN + ((TPH - 1) & 7) * 256);
        const int colbase = (ci0 + TPH - 1) * NTILE1 + lq;
        tile_top2(acc1, 0, 1, hnp, lq, colbase, b1_0, b2_0, i1_0);
        tile_top2(acc1, 2, 3, hnp, lq, colbase, b1_1, b2_1, i1_1);
    }

    #pragma unroll
    for (int o = 1; o <= 2; o <<= 1) {
        t2_merge_shfl(b1_0, b2_0, i1_0, o);
        t2_merge_shfl(b1_1, b2_1, i1_1, o);
    }

    if ((lane & 3) == 0) {
        int r = w * 16 + (lane >> 2);
        int tt = blockIdx.x * MTILE + r;
        g_s1b1[tt * KSPLIT1 + split] = b1_0;
        g_s1b2[tt * KSPLIT1 + split] = b2_0;
        g_s1i1[tt * KSPLIT1 + split] = i1_0;
        g_s1b1[(tt + 8) * KSPLIT1 + split] = b1_1;
        g_s1b2[(tt + 8) * KSPLIT1 + split] = b2_1;
        g_s1i1[(tt + 8) * KSPLIT1 + split] = i1_1;
    }
}

// merge stage-1 splits; adaptive certified margin from token/code norms
__global__ __launch_bounds__(256)
void k_resolve1() {
    int t = blockIdx.x * 256 + threadIdx.x;
    if (t >= N_TOK) return;
    float B1 = g_s1b1[t * KSPLIT1];
    float B2 = g_s1b2[t * KSPLIT1];
    int   I1 = g_s1i1[t * KSPLIT1];
    #pragma unroll
    for (int s = 1; s < KSPLIT1; s++) {
        float b1 = g_s1b1[t * KSPLIT1 + s];
        float b2 = g_s1b2[t * KSPLIT1 + s];
        int   i1 = g_s1i1[t * KSPLIT1 + s];
        if (b1 > B1) { B2 = fmaxf(B1, b2); B1 = b1; I1 = i1; }
        else { B2 = fmaxf(B2, b1); }
    }
    g_idx[t] = I1;
    float xn = sqrtf(g_xn2[t * 2] + g_xn2[t * 2 + 1]);
    float em = sqrtf(__uint_as_float(g_emaxbits & 0x7FFFFFFFu));
    float margin = 0.001953125f * xn * em * 1.002f + 2e-3f;
    if (B1 - B2 < margin) {
        int slot = atomicAdd(&g_nflag, 1);
        g_list[slot] = t;
    }
}

// ---------------------------------------------------------------------------
__global__ __launch_bounds__(256)
void k_pack(const float* __restrict__ z) {
    int nf = g_nflag;
    int total = nf * C_DIM;
    for (int i = blockIdx.x * 256 + threadIdx.x; i < total; i += gridDim.x * 256) {
        int li = i >> 6, c = i & 63;
        int t = g_list[li];
        float x = z[(size_t)(t >> 10) * (C_DIM * HW) + c * HW + (t & 1023)];
        __half h = __float2half_rn(x);
        g_Ph[i] = h;
        g_Pr[i] = __float2half_rn(x - __half2float(h));
    }
}

// ---------------------------------------------------------------------------
// STAGE 2: 3-term scores for flagged tokens over one K-slice (16 tiles).
__global__ void __launch_bounds__(TPB, 1) k_dist2() {
    const int nf = g_nflag;
    if ((int)blockIdx.x * MTILE >= nf) return;

    extern __shared__ char smem[];
    const uint32_t sb = smem_u32(smem);
    const int tid = threadIdx.x;
    const int lane = tid & 31;
    const int w = tid >> 5;
    const int slice = blockIdx.y;
    const int ci0 = slice * TPSLICE;
    const int ci1 = ci0 + TPSLICE;

    {
        int r = tid & 127;
        int half = tid >> 7;
        int li = blockIdx.x * MTILE + r;
        size_t rowo = (size_t)((li < nf) ? li : 0) * C_DIM;
        const uint4* srch = (const uint4*)(g_Ph + rowo);
        const uint4* srcr = (const uint4*)(g_Pr + rowo);
        #pragma unroll
        for (int j = 0; j < 4; j++) {
            int chunk = half * 4 + j;
            uint32_t off = sw128((uint32_t)(r * 128 + chunk * 16));
            *(uint4*)(smem + SM_A + off) = srch[chunk];
            *(uint4*)(smem + SM_A + 16384 + off) = srcr[chunk];
        }
    }
    __syncthreads();

    u32 afr[2][4][4];
    {
        int arow = w * 16 + (lane & 7) + ((lane >> 3) & 1) * 8;
        int akb  = (lane >> 4) * 16;
        #pragma unroll
        for (int c = 0; c < 2; c++)
            #pragma unroll
            for (int q = 0; q < 4; q++) {
                uint32_t addr = sb + SM_A + c * 16384 +
                                sw128((uint32_t)(arow * 128 + q * 32 + akb));
                ldsm4(afr[c][q][0], afr[c][q][1], afr[c][q][2], afr[c][q][3], addr);
            }
    }

    auto load_tile = [&](int tile, int bufi) {
        const char* srcs[2] = {(const char*)g_Eh, (const char*)g_Er};
        #pragma unroll
        for (int c = 0; c < 2; c++) {
            const char* src = srcs[c] + (size_t)tile * (NTILE * C_DIM * 2);
            uint32_t dst = sb + SM_B + (uint32_t)(bufi * 2 + c) * 8192u;
            #pragma unroll
            for (int u = 0; u < 2; u++) {
                uint32_t off = (uint32_t)(u * TPB + tid) * 16u;
                cp_async16(dst + sw128(off), src + off);
            }
        }
        if (tid < 16)
            cp_async16(sb + SM_HN + bufi * 256 + tid * 16,
                       (const char*)(g_hn + tile * NTILE) + tid * 16);
    };

    const int brow = (lane & 7) + ((lane >> 4) & 1) * 8;
    const int bkb  = ((lane >> 3) & 1) * 16;
    const int lq   = 2 * (lane & 3);

    float b1_0 = -3.4e38f, b2_0 = -3.4e38f;
    float b1_1 = -3.4e38f, b2_1 = -3.4e38f;
    int i1_0 = 0, i1_1 = 0;

    load_tile(ci0, 0); CP_COMMIT();
    load_tile(ci0 + 1, 1); CP_COMMIT();

    for (int ci = ci0; ci < ci1; ci++) {
        const int buf = ci & 1;
        if (ci + 1 < ci1) { CP_WAIT(1); } else { CP_WAIT(0); }
        __syncthreads();

        float acc[8][4];
        #pragma unroll
        for (int g = 0; g < 8; g++)
            #pragma unroll
            for (int v = 0; v < 4; v++) acc[g][v] = 0.0f;

        #pragma unroll
        for (int q = 0; q < 4; q++) {
            u32 bfr[8][2];
            uint32_t b0base = sb + SM_B + (uint32_t)(buf * 2) * 8192u;
            #pragma unroll
            for (int g2 = 0; g2 < 4; g2++) {
                uint32_t addr = b0base +
                    sw128((uint32_t)((g2 * 16 + brow) * 128 + q * 32 + bkb));
                ldsm4(bfr[2 * g2][0], bfr[2 * g2][1],
                      bfr[2 * g2 + 1][0], bfr[2 * g2 + 1][1], addr);
            }
            #pragma unroll
            for (int g = 0; g < 8; g++) {
                mma16816(acc[g][0], acc[g][1], acc[g][2], acc[g][3],
                         afr[0][q][0], afr[0][q][1], afr[0][q][2], afr[0][q][3],
                         bfr[g][0], bfr[g][1]);
                mma16816(acc[g][0], acc[g][1], acc[g][2], acc[g][3],
                         afr[1][q][0], afr[1][q][1], afr[1][q][2], afr[1][q][3],
                         bfr[g][0], bfr[g][1]);
            }
            uint32_t b1base = sb + SM_B + (uint32_t)(buf * 2 + 1) * 8192u;
            #pragma unroll
            for (int g2 = 0; g2 < 4; g2++) {
                uint32_t addr = b1base +
                    sw128((uint32_t)((g2 * 16 + brow) * 128 + q * 32 + bkb));
                ldsm4(bfr[2 * g2][0], bfr[2 * g2][1],
                      bfr[2 * g2 + 1][0], bfr[2 * g2 + 1][1], addr);
            }
            #pragma unroll
            for (int g = 0; g < 8; g++)
                mma16816(acc[g][0], acc[g][1], acc[g][2], acc[g][3],
                         afr[0][q][0], afr[0][q][1], afr[0][q][2], afr[0][q][3],
                         bfr[g][0], bfr[g][1]);
        }

        const float* hnp = (const float*)(smem + SM_HN + buf * 256);
        const int colbase = ci * NTILE + lq;
        tile_top2(acc, 0, 1, hnp, lq, colbase, b1_0, b2_0, i1_0);
        tile_top2(acc, 2, 3, hnp, lq, colbase, b1_1, b2_1, i1_1);

        __syncthreads();
        if (ci + 2 < ci1) { load_tile(ci + 2, buf); CP_COMMIT(); }
    }

    #pragma unroll
    for (int o = 1; o <= 2; o <<= 1) {
        t2_merge_shfl(b1_0, b2_0, i1_0, o);
        t2_merge_shfl(b1_1, b2_1, i1_1, o);
    }

    if ((lane & 3) == 0) {
        int r = w * 16 + (lane >> 2);
        #pragma unroll
        for (int pair = 0; pair < 2; pair++) {
            float pb1 = pair ? b1_1 : b1_0;
            float pb2 = pair ? b2_1 : b2_0;
            int   pi1 = pair ? i1_1 : i1_0;
            int li = blockIdx.x * MTILE + r + pair * 8;
            if (li < nf) {
                g_s2b1[li * NSLICE + slice] = pb1;
                g_s2b2[li * NSLICE + slice] = pb2;
                g_s2i1[li * NSLICE + slice] = pi1;
            }
        }
    }
}

// ---------------------------------------------------------------------------
__global__ __launch_bounds__(256)
void k_resolve2() {
    int li = blockIdx.x * 256 + threadIdx.x;
    if (li >= g_nflag) return;
    int t = g_list[li];
    float B1 = -3.4e38f, B2 = -3.4e38f;
    int I1 = 0;
    #pragma unroll
    for (int s = 0; s < NSLICE; s++) {
        float b1 = g_s2b1[li * NSLICE + s];
        float b2 = g_s2b2[li * NSLICE + s];
        int   i1 = g_s2i1[li * NSLICE + s];
        if (b1 > B1) { B2 = fmaxf(B1, b2); B1 = b1; I1 = i1; }
        else { B2 = fmaxf(B2, b1); }
    }
    g_idx[t] = I1;
    if (B1 - B2 < MARGIN2) {
        g_flag2[t] = 1;
        g_key[t] = 0xFFFFFFFFFFFFFFFFULL;
        int slot = atomicAdd(&g_nflag2, 1);
        g_list2[slot] = t;
    }
}

// ---------------------------------------------------------------------------
__global__ __launch_bounds__(256)
void k_refine(const float* __restrict__ z, const float* __restrict__ emb) {
    __shared__ float sx[C_DIM];
    __shared__ u64 rk[8];
    const int tid = threadIdx.x;
    const int lane = tid & 31;
    const int wid = tid >> 5;
    const int nf = g_nflag2;
    if (nf == 0) return;

    for (int wk = blockIdx.x; wk < nf * 64; wk += gridDim.x) {
        const int it = wk >> 6;
        const int slice = wk & 63;
        const int t = g_list2[it];
        __syncthreads();
        if (tid < C_DIM) {
            const float* zp = z + (size_t)(t >> 10) * (C_DIM * HW) + (t & 1023);
            sx[tid] = zp[tid * HW];
        }
        __syncthreads();

        u64 key = 0xFFFFFFFFFFFFFFFFULL;
        if (tid < 128) {
            int k = slice * 128 + tid;
            const float4* e4 = (const float4*)(emb + (size_t)k * C_DIM);
            float s = 0.0f;
            #pragma unroll
            for (int j = 0; j < 16; j++) {
                float4 e = e4[j];
                s += sx[4 * j] * e.x + sx[4 * j + 1] * e.y
                   + sx[4 * j + 2] * e.z + sx[4 * j + 3] * e.w;
            }
            s -= g_hn[k];
            key = ((u64)(~fmono(s)) << 32) | (u32)k;
        }
        #pragma unroll
        for (int o = 16; o > 0; o >>= 1) {
            u64 ok = __shfl_xor_sync(0xffffffffu, key, o);
            if (ok < key) key = ok;
        }
        if (lane == 0) rk[wid] = key;
        __syncthreads();
        if (tid == 0) {
            u64 kmin = rk[0];
            #pragma unroll
            for (int w2 = 1; w2 < 8; w2++) if (rk[w2] < kmin) kmin = rk[w2];
            atomicMin(&g_key[t], kmin);
        }
    }
}

// ---------------------------------------------------------------------------
__global__ __launch_bounds__(256)
void k_epi(const float* __restrict__ z, const float* __restrict__ emb,
           float* __restrict__ out) {
    const int gid = blockIdx.x * blockDim.x + threadIdx.x;
    const int t = gid >> 2;
    const int part = gid & 3;
    if (t >= N_TOK) return;
    const int b = t >> 10;
    const int hw = t & 1023;
    const float* zp = z + (size_t)b * (C_DIM * HW) + hw;

    int bi = g_flag2[t] ? (int)(u32)(g_key[t] & 0xFFFFFFFFULL) : g_idx[t];
    if (part == 0) {
        out[O_IDX + t] = (float)bi;
        atomicAdd(&g_counts[bi], 1.0f);
    }

    const float4* er = (const float4*)(emb + (size_t)bi * C_DIM) + part * 4;
    float* dwp = g_dw + (size_t)bi * C_DIM;
    float* zq   = out + O_ZQ   + (size_t)b * (C_DIM * HW) + hw;
    float* zqst = out + O_ZQST + (size_t)b * (C_DIM * HW) + hw;

    #pragma unroll
    for (int j = 0; j < 4; j++) {
        float4 q = er[j];
        int c = part * 16 + 4 * j;
        float x0 = zp[(c + 0) * HW];
        float x1 = zp[(c + 1) * HW];
        float x2 = zp[(c + 2) * HW];
        float x3 = zp[(c + 3) * HW];
        zq[(c + 0) * HW] = q.x;
        zq[(c + 1) * HW] = q.y;
        zq[(c + 2) * HW] = q.z;
        zq[(c + 3) * HW] = q.w;
        zqst[(c + 0) * HW] = x0 + (q.x - x0);
        zqst[(c + 1) * HW] = x1 + (q.y - x1);
        zqst[(c + 2) * HW] = x2 + (q.z - x2);
        zqst[(c + 3) * HW] = x3 + (q.w - x3);
        atomicAdd(dwp + c + 0, x0);
        atomicAdd(dwp + c + 1, x1);
        atomicAdd(dwp + c + 2, x2);
        atomicAdd(dwp + c + 3, x3);
    }
}

// ---------------------------------------------------------------------------
__global__ __launch_bounds__(256)
void k_cs(const float* __restrict__ cs, float* __restrict__ out) {
    const float OMD = 0.01f;
    int i = blockIdx.x * 256 + threadIdx.x;
    float v = 0.99f * cs[i] + OMD * g_counts[i];
    out[O_CS + i] = v;
    #pragma unroll
    for (int o = 16; o > 0; o >>= 1) v += __shfl_xor_sync(0xffffffffu, v, o);
    __shared__ float red[8];
    if ((threadIdx.x & 31) == 0) red[threadIdx.x >> 5] = v;
    __syncthreads();
    if (threadIdx.x == 0) {
        float s = red[0];
        #pragma unroll
        for (int w2 = 1; w2 < 8; w2++) s += red[w2];
        atomicAdd(&g_n, s);
    }
}

__global__ void k_emb(const float* __restrict__ cs, const float* __restrict__ avg,
                      float* __restrict__ out) {
    const float OMD = 0.01f;
    const float EPSF = 1e-5f;
    int i = blockIdx.x * blockDim.x + threadIdx.x;
    if (i >= K_CODES * C_DIM) return;
    int k = i >> 6;
    float ncs = 0.99f * cs[k] + OMD * g_counts[k];
    float navg = 0.99f * avg[i] + OMD * g_dw[i];
    float n = g_n;
    float denom = (ncs + EPSF) / (n + (float)K_CODES * EPSF) * n;
    out[O_EMB + i] = navg / denom;
    out[O_AVG + i] = navg;
}

// ---------------------------------------------------------------------------
extern "C" void kernel_launch(void* const* d_in, const int* in_sizes, int n_in,
                              void* d_out, int out_size) {
    const float* z   = (const float*)d_in[0];
    const float* emb = (const float*)d_in[1];
    const float* cs  = (const float*)d_in[2];
    const float* avg = (const float*)d_in[3];
    float* out = (float*)d_out;

    cudaFuncSetAttribute(k_dist1, cudaFuncAttributeMaxDynamicSharedMemorySize, SMEM1_TOTAL);
    cudaFuncSetAttribute(k_dist2, cudaFuncAttributeMaxDynamicSharedMemorySize, SMEM2_TOTAL);

    k_initA<<<(K_CODES * C_DIM + 255) / 256, 256>>>();                     // 1
    k_initB<<<(N_TOK + 255) / 256, 256>>>();                               // 2
    k_splitE<<<(K_CODES * 32 + 255) / 256, 256>>>(emb);                    // 3
    k_dist1<<<dim3(N_TOK / MTILE, KSPLIT1), TPB, SMEM1_TOTAL>>>(z);        // 4 <- profiled
    k_resolve1<<<N_TOK / 256, 256>>>();                                    // 5
    k_pack<<<256, 256>>>(z);                                               // 6
    k_dist2<<<dim3(N_TOK / MTILE, NSLICE), TPB, SMEM2_TOTAL>>>();          // 7
    k_resolve2<<<N_TOK / 256, 256>>>();                                    // 8
    k_refine<<<128, 256>>>(z, emb);                                        // 9
    k_epi<<<(4 * N_TOK + 255) / 256, 256>>>(z, emb, out);                  // 10
    k_cs<<<K_CODES / 256, 256>>>(cs, out);                                 // 11
    k_emb<<<(K_CODES * C_DIM + 255) / 256, 256>>>(cs, avg, out);           // 12
}

// round 16
// speedup vs baseline: 1.0418x; 1.0418x over previous
#include <cuda_runtime.h>
#include <cuda_fp16.h>
#include <cstdint>

#define K_CODES 8192
#define C_DIM   64
#define N_TOK   16384
#define HW      1024
#define TPB     256
#define MTILE   128
// stage 1 tiling
#define NTILE1  64
#define NTILES1 (K_CODES / NTILE1)   // 128
#define KSPLIT1 4
#define TPH     (NTILES1 / KSPLIT1)  // 32 tiles per K-split
// stage 2 tiling
#define NTILE   64
#define NTILES  (K_CODES / NTILE)    // 128
#define NSLICE  8
#define TPSLICE (NTILES / NSLICE)    // 16
#define MARGIN2 1e-4f                // proven R5-R15

#define O_ZQST 0
#define O_IDX  1048576
#define O_ZQ   1064960
#define O_EMB  2113536
#define O_CS   2637824
#define O_AVG  2646016

// stage-1 smem: A 16KB, B 4x8KB ring, hn 4x256B
#define SM1_A   0
#define SM1_B   16384
#define SM1_HN  49152
#define SMEM1_TOTAL (49152 + 1024 + 128)

// stage-2 smem
#define SM_A    0
#define SM_B    32768
#define SM_HN   65536
#define SMEM2_TOTAL (65536 + 512 + 128)

typedef unsigned long long u64;
typedef unsigned int u32;

static __device__ __half g_Eh[K_CODES * C_DIM];
static __device__ __half g_Er[K_CODES * C_DIM];
static __device__ __half g_Ph[N_TOK * C_DIM];
static __device__ __half g_Pr[N_TOK * C_DIM];
static __device__ float g_hn[K_CODES];
static __device__ float g_xn2[N_TOK * 2];
static __device__ u32   g_emaxbits;
static __device__ int   g_idx[N_TOK];
static __device__ int   g_flag2[N_TOK];
static __device__ u64   g_key[N_TOK];
static __device__ int   g_list[N_TOK];
static __device__ int   g_list2[N_TOK];
static __device__ int   g_nflag;
static __device__ int   g_nflag2;
static __device__ float g_s1b1[N_TOK * KSPLIT1];
static __device__ float g_s1b2[N_TOK * KSPLIT1];
static __device__ int   g_s1i1[N_TOK * KSPLIT1];
static __device__ float g_s2b1[N_TOK * NSLICE];
static __device__ float g_s2b2[N_TOK * NSLICE];
static __device__ int   g_s2i1[N_TOK * NSLICE];
static __device__ float g_counts[K_CODES];
static __device__ float g_dw[K_CODES * C_DIM];
static __device__ float g_n;

// ---------------------------------------------------------------- helpers
__device__ __forceinline__ uint32_t smem_u32(const void* p) {
    uint32_t a;
    asm("{ .reg .u64 t; cvta.to.shared.u64 t, %1; cvt.u32.u64 %0, t; }"
        : "=r"(a) : "l"(p));
    return a;
}
__device__ __forceinline__ void cp_async16(uint32_t saddr, const void* gmem) {
    asm volatile("cp.async.cg.shared.global [%0], [%1], 16;\n" :: "r"(saddr), "l"(gmem));
}
#define CP_COMMIT() asm volatile("cp.async.commit_group;\n" ::: "memory")
#define CP_WAIT(n)  asm volatile("cp.async.wait_group %0;\n" :: "n"(n) : "memory")

__device__ __forceinline__ uint32_t sw128(uint32_t off) {
    return off ^ ((off >> 3) & 0x70);
}
__device__ __forceinline__ void ldsm4(u32& r0, u32& r1, u32& r2, u32& r3, uint32_t addr) {
    asm volatile("ldmatrix.sync.aligned.m8n8.x4.shared.b16 {%0,%1,%2,%3}, [%4];"
                 : "=r"(r0), "=r"(r1), "=r"(r2), "=r"(r3) : "r"(addr));
}
__device__ __forceinline__ void mma16816(float& d0, float& d1, float& d2, float& d3,
                                         u32 a0, u32 a1, u32 a2, u32 a3,
                                         u32 b0, u32 b1) {
    asm volatile("mma.sync.aligned.m16n8k16.row.col.f32.f16.f16.f32 "
                 "{%0,%1,%2,%3}, {%4,%5,%6,%7}, {%8,%9}, {%0,%1,%2,%3};"
                 : "+f"(d0), "+f"(d1), "+f"(d2), "+f"(d3)
                 : "r"(a0), "r"(a1), "r"(a2), "r"(a3), "r"(b0), "r"(b1));
}
__device__ __forceinline__ u32 fmono(float s) {
    u32 u = __float_as_uint(s);
    return (s < 0.0f) ? ~u : (u | 0x80000000u);
}

__device__ __forceinline__ void merge2(float& m1a, float& m2a, int& ia,
                                       float m1b, float m2b, int ib) {
    float mn = fminf(m1a, m1b);
    m2a = fmaxf(mn, fmaxf(m2a, m2b));
    ia = (m1a >= m1b) ? ia : ib;
    m1a = fmaxf(m1a, m1b);
}
__device__ __forceinline__ void t2_merge_shfl(float& b1, float& b2, int& i1, int o) {
    float ob1 = __shfl_xor_sync(0xffffffffu, b1, o);
    float ob2 = __shfl_xor_sync(0xffffffffu, b2, o);
    int   oi1 = __shfl_xor_sync(0xffffffffu, i1, o);
    if (ob1 > b1 || (ob1 == b1 && oi1 < i1)) {
        b2 = fmaxf(b1, ob2); b1 = ob1; i1 = oi1;
    } else {
        b2 = fmaxf(b2, ob1);
    }
}
__device__ __forceinline__ void tile_top2(const float acc[8][4], int v0, int v1,
                                          const float* hnp, int lq, int colbase,
                                          float& b1, float& b2, int& i1) {
    float m1[8], m2[8]; int ii[8];
    #pragma unroll
    for (int g = 0; g < 8; g++) {
        int lc = g * 8 + lq;
        float sa = acc[g][v0] - hnp[lc];
        float sb = acc[g][v1] - hnp[lc + 1];
        m1[g] = fmaxf(sa, sb);
        m2[g] = fminf(sa, sb);
        ii[g] = (sa >= sb) ? (colbase + g * 8) : (colbase + g * 8 + 1);
    }
    #pragma unroll
    for (int st = 1; st < 8; st <<= 1)
        #pragma unroll
        for (int g = 0; g < 8; g += 2 * st)
            merge2(m1[g], m2[g], ii[g], m1[g + st], m2[g + st], ii[g + st]);
    merge2(b1, b2, i1, m1[0], m2[0], ii[0]);
}

// ---------------------------------------------------------------------------
__global__ void k_initA() {
    int i = blockIdx.x * blockDim.x + threadIdx.x;
    if (i < K_CODES * C_DIM) g_dw[i] = 0.0f;
}
__global__ void k_initB() {
    int i = blockIdx.x * blockDim.x + threadIdx.x;
    if (i < K_CODES) g_counts[i] = 0.0f;
    if (i < N_TOK) g_flag2[i] = 0;
    if (i == 0) { g_nflag = 0; g_nflag2 = 0; g_n = 0.0f; g_emaxbits = 0; }
}

__global__ void k_splitE(const float* __restrict__ emb) {
    int w = (blockIdx.x * blockDim.x + threadIdx.x) >> 5;
    int lane = threadIdx.x & 31;
    if (w >= K_CODES) return;
    float s = 0.0f;
    #pragma unroll
    for (int half = 0; half < 2; half++) {
        int c = lane + half * 32;
        float x = emb[w * C_DIM + c];
        s += x * x;
        __half h = __float2half_rn(x);
        float r = x - __half2float(h);
        g_Eh[w * C_DIM + c] = h;
        g_Er[w * C_DIM + c] = __float2half_rn(r);
    }
    #pragma unroll
    for (int o = 16; o > 0; o >>= 1) s += __shfl_xor_sync(0xffffffffu, s, o);
    if (lane == 0) {
        g_hn[w] = 0.5f * s;
        atomicMax(&g_emaxbits, fmono(s));
    }
}

// ---------------------------------------------------------------------------
// STAGE 1: hh scores over one K-quarter; NTILE=64, 4-stage ring, 1 sync/tile,
// decomposed B addresses, small bfr working set. grid (128, 4), 3 CTA/SM.
__global__ void __launch_bounds__(TPB, 3) k_dist1(const float* __restrict__ z) {
    extern __shared__ char smem[];
    const uint32_t sb = smem_u32(smem);
    const int tid = threadIdx.x;
    const int lane = tid & 31;
    const int w = tid >> 5;
    const int split = blockIdx.y;
    const int ci0 = split * TPH;

    {
        int r = tid & 127;
        int half = tid >> 7;
        int t = blockIdx.x * MTILE + r;
        const float* zp = z + (size_t)(t >> 10) * (C_DIM * HW) + (t & 1023);
        float s = 0.0f;
        #pragma unroll
        for (int j = 0; j < 32; j++) {
            int c = half * 32 + j;
            float x = zp[c * HW];
            s += x * x;
            uint32_t off = sw128((uint32_t)(r * 128 + c * 2));
            *(__half*)(smem + SM1_A + off) = __float2half_rn(x);
        }
        if (split == 0) g_xn2[t * 2 + half] = s;
    }
    __syncthreads();

    u32 afr[4][4];
    {
        int arow = w * 16 + (lane & 7) + ((lane >> 3) & 1) * 8;
        int akb  = (lane >> 4) * 16;
        #pragma unroll
        for (int q = 0; q < 4; q++) {
            uint32_t addr = sb + SM1_A + sw128((uint32_t)(arow * 128 + q * 32 + akb));
            ldsm4(afr[q][0], afr[q][1], afr[q][2], afr[q][3], addr);
        }
    }

    // B address decomposition (validated R15): mask depends only on brow&7
    const int brow = (lane & 7) + ((lane >> 4) & 1) * 8;
    const int bkb  = ((lane >> 3) & 1) * 16;
    const int lq   = 2 * (lane & 3);
    const uint32_t m = (uint32_t)((brow & 7) << 4);
    u32 bbase[4];
    u32 qoff[4];
    #pragma unroll
    for (int g2 = 0; g2 < 4; g2++)
        bbase[g2] = sb + SM1_B + (uint32_t)((g2 * 16 + brow) * 128)
                  + ((uint32_t)bkb ^ (m & 0x10u));
    #pragma unroll
    for (int q = 0; q < 4; q++)
        qoff[q] = ((uint32_t)(q * 32)) ^ (m & 0x60u);

    auto load_tile = [&](int tile, int stg) {
        const char* src = (const char*)g_Eh + (size_t)tile * (NTILE1 * C_DIM * 2);
        uint32_t dst = sb + SM1_B + (uint32_t)stg * 8192u;
        #pragma unroll
        for (int u = 0; u < 2; u++) {
            uint32_t off = (uint32_t)(u * TPB + tid) * 16u;
            cp_async16(dst + sw128(off), src + off);
        }
        if (tid < 16)
            cp_async16(sb + SM1_HN + stg * 256 + tid * 16,
                       (const char*)(g_hn + tile * NTILE1) + tid * 16);
    };

    float b1_0 = -3.4e38f, b2_0 = -3.4e38f;
    float b1_1 = -3.4e38f, b2_1 = -3.4e38f;
    int i1_0 = 0, i1_1 = 0;

    load_tile(ci0 + 0, 0); CP_COMMIT();
    load_tile(ci0 + 1, 1); CP_COMMIT();
    load_tile(ci0 + 2, 2); CP_COMMIT();

    for (int idx = 0; idx < TPH; idx++) {
        const int ci = ci0 + idx;
        const int stg = idx & 3;
        if (idx + 3 <= TPH)      { CP_WAIT(2); }
        else if (idx + 2 == TPH) { CP_WAIT(1); }
        else                     { CP_WAIT(0); }
        __syncthreads();
        if (idx + 3 < TPH) { load_tile(ci + 3, (idx + 3) & 3); CP_COMMIT(); }

        float acc[8][4];
        #pragma unroll
        for (int g = 0; g < 8; g++)
            #pragma unroll
            for (int v = 0; v < 4; v++) acc[g][v] = 0.0f;

        const uint32_t soff = (uint32_t)stg * 8192u;
        #pragma unroll
        for (int q = 0; q < 4; q++) {
            const uint32_t qs = qoff[q] + soff;
            // half 1: groups 0-1 (n 0..31)
            {
                u32 bfr[4][2];
                ldsm4(bfr[0][0], bfr[0][1], bfr[1][0], bfr[1][1], bbase[0] + qs);
                ldsm4(bfr[2][0], bfr[2][1], bfr[3][0], bfr[3][1], bbase[1] + qs);
                #pragma unroll
                for (int g = 0; g < 4; g++)
                    mma16816(acc[g][0], acc[g][1], acc[g][2], acc[g][3],
                             afr[q][0], afr[q][1], afr[q][2], afr[q][3],
                             bfr[g][0], bfr[g][1]);
            }
            // half 2: groups 2-3 (n 32..63)
            {
                u32 bfr[4][2];
                ldsm4(bfr[0][0], bfr[0][1], bfr[1][0], bfr[1][1], bbase[2] + qs);
                ldsm4(bfr[2][0], bfr[2][1], bfr[3][0], bfr[3][1], bbase[3] + qs);
                #pragma unroll
                for (int g = 0; g < 4; g++)
                    mma16816(acc[g + 4][0], acc[g + 4][1], acc[g + 4][2], acc[g + 4][3],
                             afr[q][0], afr[q][1], afr[q][2], afr[q][3],
                             bfr[g][0], bfr[g][1]);
            }
        }

        const float* hnp = (const float*)(smem + SM1_HN + stg * 256);
        const int colbase = ci * NTILE1 + lq;
        tile_top2(acc, 0, 1, hnp, lq, colbase, b1_0, b2_0, i1_0);
        tile_top2(acc, 2, 3, hnp, lq, colbase, b1_1, b2_1, i1_1);
    }

    #pragma unroll
    for (int o = 1; o <= 2; o <<= 1) {
        t2_merge_shfl(b1_0, b2_0, i1_0, o);
        t2_merge_shfl(b1_1, b2_1, i1_1, o);
    }

    if ((lane & 3) == 0) {
        int r = w * 16 + (lane >> 2);
        int tt = blockIdx.x * MTILE + r;
        g_s1b1[tt * KSPLIT1 + split] = b1_0;
        g_s1b2[tt * KSPLIT1 + split] = b2_0;
        g_s1i1[tt * KSPLIT1 + split] = i1_0;
        g_s1b1[(tt + 8) * KSPLIT1 + split] = b1_1;
        g_s1b2[(tt + 8) * KSPLIT1 + split] = b2_1;
        g_s1i1[(tt + 8) * KSPLIT1 + split] = i1_1;
    }
}

// merge stage-1 splits; adaptive certified margin from token/code norms
__global__ __launch_bounds__(256)
void k_resolve1() {
    int t = blockIdx.x * 256 + threadIdx.x;
    if (t >= N_TOK) return;
    float B1 = g_s1b1[t * KSPLIT1];
    float B2 = g_s1b2[t * KSPLIT1];
    int   I1 = g_s1i1[t * KSPLIT1];
    #pragma unroll
    for (int s = 1; s < KSPLIT1; s++) {
        float b1 = g_s1b1[t * KSPLIT1 + s];
        float b2 = g_s1b2[t * KSPLIT1 + s];
        int   i1 = g_s1i1[t * KSPLIT1 + s];
        if (b1 > B1) { B2 = fmaxf(B1, b2); B1 = b1; I1 = i1; }
        else { B2 = fmaxf(B2, b1); }
    }
    g_idx[t] = I1;
    float xn = sqrtf(g_xn2[t * 2] + g_xn2[t * 2 + 1]);
    float em = sqrtf(__uint_as_float(g_emaxbits & 0x7FFFFFFFu));
    float margin = 0.001953125f * xn * em * 1.002f + 2e-3f;
    if (B1 - B2 < margin) {
        int slot = atomicAdd(&g_nflag, 1);
        g_list[slot] = t;
    }
}

// ---------------------------------------------------------------------------
__global__ __launch_bounds__(256)
void k_pack(const float* __restrict__ z) {
    int nf = g_nflag;
    int total = nf * C_DIM;
    for (int i = blockIdx.x * 256 + threadIdx.x; i < total; i += gridDim.x * 256) {
        int li = i >> 6, c = i & 63;
        int t = g_list[li];
        float x = z[(size_t)(t >> 10) * (C_DIM * HW) + c * HW + (t & 1023)];
        __half h = __float2half_rn(x);
        g_Ph[i] = h;
        g_Pr[i] = __float2half_rn(x - __half2float(h));
    }
}

// ---------------------------------------------------------------------------
// STAGE 2: 3-term scores for flagged tokens over one K-slice (16 tiles).
__global__ void __launch_bounds__(TPB, 1) k_dist2() {
    const int nf = g_nflag;
    if ((int)blockIdx.x * MTILE >= nf) return;

    extern __shared__ char smem[];
    const uint32_t sb = smem_u32(smem);
    const int tid = threadIdx.x;
    const int lane = tid & 31;
    const int w = tid >> 5;
    const int slice = blockIdx.y;
    const int ci0 = slice * TPSLICE;
    const int ci1 = ci0 + TPSLICE;

    {
        int r = tid & 127;
        int half = tid >> 7;
        int li = blockIdx.x * MTILE + r;
        size_t rowo = (size_t)((li < nf) ? li : 0) * C_DIM;
        const uint4* srch = (const uint4*)(g_Ph + rowo);
        const uint4* srcr = (const uint4*)(g_Pr + rowo);
        #pragma unroll
        for (int j = 0; j < 4; j++) {
            int chunk = half * 4 + j;
            uint32_t off = sw128((uint32_t)(r * 128 + chunk * 16));
            *(uint4*)(smem + SM_A + off) = srch[chunk];
            *(uint4*)(smem + SM_A + 16384 + off) = srcr[chunk];
        }
    }
    __syncthreads();

    u32 afr[2][4][4];
    {
        int arow = w * 16 + (lane & 7) + ((lane >> 3) & 1) * 8;
        int akb  = (lane >> 4) * 16;
        #pragma unroll
        for (int c = 0; c < 2; c++)
            #pragma unroll
            for (int q = 0; q < 4; q++) {
                uint32_t addr = sb + SM_A + c * 16384 +
                                sw128((uint32_t)(arow * 128 + q * 32 + akb));
                ldsm4(afr[c][q][0], afr[c][q][1], afr[c][q][2], afr[c][q][3], addr);
            }
    }

    auto load_tile = [&](int tile, int bufi) {
        const char* srcs[2] = {(const char*)g_Eh, (const char*)g_Er};
        #pragma unroll
        for (int c = 0; c < 2; c++) {
            const char* src = srcs[c] + (size_t)tile * (NTILE * C_DIM * 2);
            uint32_t dst = sb + SM_B + (uint32_t)(bufi * 2 + c) * 8192u;
            #pragma unroll
            for (int u = 0; u < 2; u++) {
                uint32_t off = (uint32_t)(u * TPB + tid) * 16u;
                cp_async16(dst + sw128(off), src + off);
            }
        }
        if (tid < 16)
            cp_async16(sb + SM_HN + bufi * 256 + tid * 16,
                       (const char*)(g_hn + tile * NTILE) + tid * 16);
    };

    const int brow = (lane & 7) + ((lane >> 4) & 1) * 8;
    const int bkb  = ((lane >> 3) & 1) * 16;
    const int lq   = 2 * (lane & 3);

    float b1_0 = -3.4e38f, b2_0 = -3.4e38f;
    float b1_1 = -3.4e38f, b2_1 = -3.4e38f;
    int i1_0 = 0, i1_1 = 0;

    load_tile(ci0, 0); CP_COMMIT();
    load_tile(ci0 + 1, 1); CP_COMMIT();

    for (int ci = ci0; ci < ci1; ci++) {
        const int buf = ci & 1;
        if (ci + 1 < ci1) { CP_WAIT(1); } else { CP_WAIT(0); }
        __syncthreads();

        float acc[8][4];
        #pragma unroll
        for (int g = 0; g < 8; g++)
            #pragma unroll
            for (int v = 0; v < 4; v++) acc[g][v] = 0.0f;

        #pragma unroll
        for (int q = 0; q < 4; q++) {
            u32 bfr[8][2];
            uint32_t b0base = sb + SM_B + (uint32_t)(buf * 2) * 8192u;
            #pragma unroll
            for (int g2 = 0; g2 < 4; g2++) {
                uint32_t addr = b0base +
                    sw128((uint32_t)((g2 * 16 + brow) * 128 + q * 32 + bkb));
                ldsm4(bfr[2 * g2][0], bfr[2 * g2][1],
                      bfr[2 * g2 + 1][0], bfr[2 * g2 + 1][1], addr);
            }
            #pragma unroll
            for (int g = 0; g < 8; g++) {
                mma16816(acc[g][0], acc[g][1], acc[g][2], acc[g][3],
                         afr[0][q][0], afr[0][q][1], afr[0][q][2], afr[0][q][3],
                         bfr[g][0], bfr[g][1]);
                mma16816(acc[g][0], acc[g][1], acc[g][2], acc[g][3],
                         afr[1][q][0], afr[1][q][1], afr[1][q][2], afr[1][q][3],
                         bfr[g][0], bfr[g][1]);
            }
            uint32_t b1base = sb + SM_B + (uint32_t)(buf * 2 + 1) * 8192u;
            #pragma unroll
            for (int g2 = 0; g2 < 4; g2++) {
                uint32_t addr = b1base +
                    sw128((uint32_t)((g2 * 16 + brow) * 128 + q * 32 + bkb));
                ldsm4(bfr[2 * g2][0], bfr[2 * g2][1],
                      bfr[2 * g2 + 1][0], bfr[2 * g2 + 1][1], addr);
            }
            #pragma unroll
            for (int g = 0; g < 8; g++)
                mma16816(acc[g][0], acc[g][1], acc[g][2], acc[g][3],
                         afr[0][q][0], afr[0][q][1], afr[0][q][2], afr[0][q][3],
                         bfr[g][0], bfr[g][1]);
        }

        const float* hnp = (const float*)(smem + SM_HN + buf * 256);
        const int colbase = ci * NTILE + lq;
        tile_top2(acc, 0, 1, hnp, lq, colbase, b1_0, b2_0, i1_0);
        tile_top2(acc, 2, 3, hnp, lq, colbase, b1_1, b2_1, i1_1);

        __syncthreads();
        if (ci + 2 < ci1) { load_tile(ci + 2, buf); CP_COMMIT(); }
    }

    #pragma unroll
    for (int o = 1; o <= 2; o <<= 1) {
        t2_merge_shfl(b1_0, b2_0, i1_0, o);
        t2_merge_shfl(b1_1, b2_1, i1_1, o);
    }

    if ((lane & 3) == 0) {
        int r = w * 16 + (lane >> 2);
        #pragma unroll
        for (int pair = 0; pair < 2; pair++) {
            float pb1 = pair ? b1_1 : b1_0;
            float pb2 = pair ? b2_1 : b2_0;
            int   pi1 = pair ? i1_1 : i1_0;
            int li = blockIdx.x * MTILE + r + pair * 8;
            if (li < nf) {
                g_s2b1[li * NSLICE + slice] = pb1;
                g_s2b2[li * NSLICE + slice] = pb2;
                g_s2i1[li * NSLICE + slice] = pi1;
            }
        }
    }
}

// ---------------------------------------------------------------------------
__global__ __launch_bounds__(256)
void k_resolve2() {
    int li = blockIdx.x * 256 + threadIdx.x;
    if (li >= g_nflag) return;
    int t = g_list[li];
    float B1 = -3.4e38f, B2 = -3.4e38f;
    int I1 = 0;
    #pragma unroll
    for (int s = 0; s < NSLICE; s++) {
        float b1 = g_s2b1[li * NSLICE + s];
        float b2 = g_s2b2[li * NSLICE + s];
        int   i1 = g_s2i1[li * NSLICE + s];
        if (b1 > B1) { B2 = fmaxf(B1, b2); B1 = b1; I1 = i1; }
        else { B2 = fmaxf(B2, b1); }
    }
    g_idx[t] = I1;
    if (B1 - B2 < MARGIN2) {
        g_flag2[t] = 1;
        g_key[t] = 0xFFFFFFFFFFFFFFFFULL;
        int slot = atomicAdd(&g_nflag2, 1);
        g_list2[slot] = t;
    }
}

// ---------------------------------------------------------------------------
__global__ __launch_bounds__(256)
void k_refine(const float* __restrict__ z, const float* __restrict__ emb) {
    __shared__ float sx[C_DIM];
    __shared__ u64 rk[8];
    const int tid = threadIdx.x;
    const int lane = tid & 31;
    const int wid = tid >> 5;
    const int nf = g_nflag2;
    if (nf == 0) return;

    for (int wk = blockIdx.x; wk < nf * 64; wk += gridDim.x) {
        const int it = wk >> 6;
        const int slice = wk & 63;
        const int t = g_list2[it];
        __syncthreads();
        if (tid < C_DIM) {
            const float* zp = z + (size_t)(t >> 10) * (C_DIM * HW) + (t & 1023);
            sx[tid] = zp[tid * HW];
        }
        __syncthreads();

        u64 key = 0xFFFFFFFFFFFFFFFFULL;
        if (tid < 128) {
            int k = slice * 128 + tid;
            const float4* e4 = (const float4*)(emb + (size_t)k * C_DIM);
            float s = 0.0f;
            #pragma unroll
            for (int j = 0; j < 16; j++) {
                float4 e = e4[j];
                s += sx[4 * j] * e.x + sx[4 * j + 1] * e.y
                   + sx[4 * j + 2] * e.z + sx[4 * j + 3] * e.w;
            }
            s -= g_hn[k];
            key = ((u64)(~fmono(s)) << 32) | (u32)k;
        }
        #pragma unroll
        for (int o = 16; o > 0; o >>= 1) {
            u64 ok = __shfl_xor_sync(0xffffffffu, key, o);
            if (ok < key) key = ok;
        }
        if (lane == 0) rk[wid] = key;
        __syncthreads();
        if (tid == 0) {
            u64 kmin = rk[0];
            #pragma unroll
            for (int w2 = 1; w2 < 8; w2++) if (rk[w2] < kmin) kmin = rk[w2];
            atomicMin(&g_key[t], kmin);
        }
    }
}

// ---------------------------------------------------------------------------
__global__ __launch_bounds__(256)
void k_epi(const float* __restrict__ z, const float* __restrict__ emb,
           float* __restrict__ out) {
    const int gid = blockIdx.x * blockDim.x + threadIdx.x;
    const int t = gid >> 2;
    const int part = gid & 3;
    if (t >= N_TOK) return;
    const int b = t >> 10;
    const int hw = t & 1023;
    const float* zp = z + (size_t)b * (C_DIM * HW) + hw;

    int bi = g_flag2[t] ? (int)(u32)(g_key[t] & 0xFFFFFFFFULL) : g_idx[t];
    if (part == 0) {
        out[O_IDX + t] = (float)bi;
        atomicAdd(&g_counts[bi], 1.0f);
    }

    const float4* er = (const float4*)(emb + (size_t)bi * C_DIM) + part * 4;
    float* dwp = g_dw + (size_t)bi * C_DIM;
    float* zq   = out + O_ZQ   + (size_t)b * (C_DIM * HW) + hw;
    float* zqst = out + O_ZQST + (size_t)b * (C_DIM * HW) + hw;

    #pragma unroll
    for (int j = 0; j < 4; j++) {
        float4 q = er[j];
        int c = part * 16 + 4 * j;
        float x0 = zp[(c + 0) * HW];
        float x1 = zp[(c + 1) * HW];
        float x2 = zp[(c + 2) * HW];
        float x3 = zp[(c + 3) * HW];
        zq[(c + 0) * HW] = q.x;
        zq[(c + 1) * HW] = q.y;
        zq[(c + 2) * HW] = q.z;
        zq[(c + 3) * HW] = q.w;
        zqst[(c + 0) * HW] = x0 + (q.x - x0);
        zqst[(c + 1) * HW] = x1 + (q.y - x1);
        zqst[(c + 2) * HW] = x2 + (q.z - x2);
        zqst[(c + 3) * HW] = x3 + (q.w - x3);
        atomicAdd(dwp + c + 0, x0);
        atomicAdd(dwp + c + 1, x1);
        atomicAdd(dwp + c + 2, x2);
        atomicAdd(dwp + c + 3, x3);
    }
}

// ---------------------------------------------------------------------------
__global__ __launch_bounds__(256)
void k_cs(const float* __restrict__ cs, float* __restrict__ out) {
    const float OMD = 0.01f;
    int i = blockIdx.x * 256 + threadIdx.x;
    float v = 0.99f * cs[i] + OMD * g_counts[i];
    out[O_CS + i] = v;
    #pragma unroll
    for (int o = 16; o > 0; o >>= 1) v += __shfl_xor_sync(0xffffffffu, v, o);
    __shared__ float red[8];
    if ((threadIdx.x & 31) == 0) red[threadIdx.x >> 5] = v;
    __syncthreads();
    if (threadIdx.x == 0) {
        float s = red[0];
        #pragma unroll
        for (int w2 = 1; w2 < 8; w2++) s += red[w2];
        atomicAdd(&g_n, s);
    }
}

__global__ void k_emb(const float* __restrict__ cs, const float* __restrict__ avg,
                      float* __restrict__ out) {
    const float OMD = 0.01f;
    const float EPSF = 1e-5f;
    int i = blockIdx.x * blockDim.x + threadIdx.x;
    if (i >= K_CODES * C_DIM) return;
    int k = i >> 6;
    float ncs = 0.99f * cs[k] + OMD * g_counts[k];
    float navg = 0.99f * avg[i] + OMD * g_dw[i];
    float n = g_n;
    float denom = (ncs + EPSF) / (n + (float)K_CODES * EPSF) * n;
    out[O_EMB + i] = navg / denom;
    out[O_AVG + i] = navg;
}

// ---------------------------------------------------------------------------
extern "C" void kernel_launch(void* const* d_in, const int* in_sizes, int n_in,
                              void* d_out, int out_size) {
    const float* z   = (const float*)d_in[0];
    const float* emb = (const float*)d_in[1];
    const float* cs  = (const float*)d_in[2];
    const float* avg = (const float*)d_in[3];
    float* out = (float*)d_out;

    cudaFuncSetAttribute(k_dist1, cudaFuncAttributeMaxDynamicSharedMemorySize, SMEM1_TOTAL);
    cudaFuncSetAttribute(k_dist2, cudaFuncAttributeMaxDynamicSharedMemorySize, SMEM2_TOTAL);

    k_initA<<<(K_CODES * C_DIM + 255) / 256, 256>>>();                     // 1
    k_initB<<<(N_TOK + 255) / 256, 256>>>();                               // 2
    k_splitE<<<(K_CODES * 32 + 255) / 256, 256>>>(emb);                    // 3
    k_dist1<<<dim3(N_TOK / MTILE, KSPLIT1), TPB, SMEM1_TOTAL>>>(z);        // 4 <- profiled
    k_resolve1<<<N_TOK / 256, 256>>>();                                    // 5
    k_pack<<<256, 256>>>(z);                                               // 6
    k_dist2<<<dim3(N_TOK / MTILE, NSLICE), TPB, SMEM2_TOTAL>>>();          // 7
    k_resolve2<<<N_TOK / 256, 256>>>();                                    // 8
    k_refine<<<128, 256>>>(z, emb);                                        // 9
    k_epi<<<(4 * N_TOK + 255) / 256, 256>>>(z, emb, out);                  // 10
    k_cs<<<K_CODES / 256, 256>>>(cs, out);                                 // 11
    k_emb<<<(K_CODES * C_DIM + 255) / 256, 256>>>(cs, avg, out);           // 12
}

// round 17
// speedup vs baseline: 1.1055x; 1.0611x over previous
#include <cuda_runtime.h>
#include <cuda_fp16.h>
#include <cstdint>

#define K_CODES 8192
#define C_DIM   64
#define N_TOK   16384
#define HW      1024
#define TPB     256
#define MTILE   128
// stage 1 tiling
#define NTILE1  64
#define NTILES1 (K_CODES / NTILE1)   // 128
#define KSPLIT1 4
#define TPH     (NTILES1 / KSPLIT1)  // 32
// stage 2 tiling
#define NTILE   64
#define NTILES  (K_CODES / NTILE)    // 128
#define NSLICE  8
#define TPSLICE (NTILES / NSLICE)    // 16
#define MARGIN2 1e-4f                // proven R5-R16

#define O_ZQST 0
#define O_IDX  1048576
#define O_ZQ   1064960
#define O_EMB  2113536
#define O_CS   2637824
#define O_AVG  2646016

// stage-1 smem: A 16KB, B 4x8KB ring, hn 4x256B
#define SM1_A   0
#define SM1_B   16384
#define SM1_HN  49152
#define SMEM1_TOTAL (49152 + 1024 + 128)

// stage-2 smem
#define SM_A    0
#define SM_B    32768
#define SM_HN   65536
#define SMEM2_TOTAL (65536 + 512 + 128)

typedef unsigned long long u64;
typedef unsigned int u32;

static __device__ __half g_Eh[K_CODES * C_DIM];
static __device__ __half g_Er[K_CODES * C_DIM];
static __device__ __half g_Ph[N_TOK * C_DIM];
static __device__ __half g_Pr[N_TOK * C_DIM];
static __device__ float g_hn[K_CODES];
static __device__ float g_xn2[N_TOK * 2];
static __device__ u32   g_emaxbits;
static __device__ int   g_idx[N_TOK];
static __device__ int   g_flag2[N_TOK];
static __device__ u64   g_key[N_TOK];
static __device__ int   g_list[N_TOK];
static __device__ int   g_list2[N_TOK];
static __device__ int   g_nflag;
static __device__ int   g_nflag2;
static __device__ float g_s1b1[N_TOK * KSPLIT1];
static __device__ float g_s1b2[N_TOK * KSPLIT1];
static __device__ int   g_s1i1[N_TOK * KSPLIT1];
static __device__ float g_s2b1[N_TOK * NSLICE];
static __device__ float g_s2b2[N_TOK * NSLICE];
static __device__ int   g_s2i1[N_TOK * NSLICE];
static __device__ float g_counts[K_CODES];
static __device__ float g_dw[K_CODES * C_DIM];
static __device__ float g_n;

// ---------------------------------------------------------------- helpers
__device__ __forceinline__ uint32_t smem_u32(const void* p) {
    uint32_t a;
    asm("{ .reg .u64 t; cvta.to.shared.u64 t, %1; cvt.u32.u64 %0, t; }"
        : "=r"(a) : "l"(p));
    return a;
}
__device__ __forceinline__ void cp_async16(uint32_t saddr, const void* gmem) {
    asm volatile("cp.async.cg.shared.global [%0], [%1], 16;\n" :: "r"(saddr), "l"(gmem));
}
#define CP_COMMIT() asm volatile("cp.async.commit_group;\n" ::: "memory")
#define CP_WAIT(n)  asm volatile("cp.async.wait_group %0;\n" :: "n"(n) : "memory")

__device__ __forceinline__ uint32_t sw128(uint32_t off) {
    return off ^ ((off >> 3) & 0x70);
}
__device__ __forceinline__ void ldsm4(u32& r0, u32& r1, u32& r2, u32& r3, uint32_t addr) {
    asm volatile("ldmatrix.sync.aligned.m8n8.x4.shared.b16 {%0,%1,%2,%3}, [%4];"
                 : "=r"(r0), "=r"(r1), "=r"(r2), "=r"(r3) : "r"(addr));
}
__device__ __forceinline__ void mma16816(float& d0, float& d1, float& d2, float& d3,
                                         u32 a0, u32 a1, u32 a2, u32 a3,
                                         u32 b0, u32 b1) {
    asm volatile("mma.sync.aligned.m16n8k16.row.col.f32.f16.f16.f32 "
                 "{%0,%1,%2,%3}, {%4,%5,%6,%7}, {%8,%9}, {%0,%1,%2,%3};"
                 : "+f"(d0), "+f"(d1), "+f"(d2), "+f"(d3)
                 : "r"(a0), "r"(a1), "r"(a2), "r"(a3), "r"(b0), "r"(b1));
}
__device__ __forceinline__ u32 fmono(float s) {
    u32 u = __float_as_uint(s);
    return (s < 0.0f) ? ~u : (u | 0x80000000u);
}

__device__ __forceinline__ void merge2(float& m1a, float& m2a, int& ia,
                                       float m1b, float m2b, int ib) {
    float mn = fminf(m1a, m1b);
    m2a = fmaxf(mn, fmaxf(m2a, m2b));
    ia = (m1a >= m1b) ? ia : ib;
    m1a = fmaxf(m1a, m1b);
}
__device__ __forceinline__ void t2_merge_shfl(float& b1, float& b2, int& i1, int o) {
    float ob1 = __shfl_xor_sync(0xffffffffu, b1, o);
    float ob2 = __shfl_xor_sync(0xffffffffu, b2, o);
    int   oi1 = __shfl_xor_sync(0xffffffffu, i1, o);
    if (ob1 > b1 || (ob1 == b1 && oi1 < i1)) {
        b2 = fmaxf(b1, ob2); b1 = ob1; i1 = oi1;
    } else {
        b2 = fmaxf(b2, ob1);
    }
}
__device__ __forceinline__ void tile_top2(const float acc[8][4], int v0, int v1,
                                          const float* hnp, int lq, int colbase,
                                          float& b1, float& b2, int& i1) {
    float m1[8], m2[8]; int ii[8];
    #pragma unroll
    for (int g = 0; g < 8; g++) {
        int lc = g * 8 + lq;
        float sa = acc[g][v0] - hnp[lc];
        float sb = acc[g][v1] - hnp[lc + 1];
        m1[g] = fmaxf(sa, sb);
        m2[g] = fminf(sa, sb);
        ii[g] = (sa >= sb) ? (colbase + g * 8) : (colbase + g * 8 + 1);
    }
    #pragma unroll
    for (int st = 1; st < 8; st <<= 1)
        #pragma unroll
        for (int g = 0; g < 8; g += 2 * st)
            merge2(m1[g], m2[g], ii[g], m1[g + st], m2[g + st], ii[g + st]);
    merge2(b1, b2, i1, m1[0], m2[0], ii[0]);
}

// ---------------------------------------------------------------------------
// fused setup: zero scratch + split E into fp16 h/r + half norms + max norm
__global__ void k_setup(const float* __restrict__ emb) {
    int i = blockIdx.x * blockDim.x + threadIdx.x;   // grid 2048*256 = 524288
    g_dw[i] = 0.0f;
    if (i < K_CODES) g_counts[i] = 0.0f;
    if (i < N_TOK) g_flag2[i] = 0;
    if (i == 0) { g_nflag = 0; g_nflag2 = 0; g_n = 0.0f; g_emaxbits = 0; }

    int w = i >> 5;
    int lane = i & 31;
    if (w < K_CODES) {
        float s = 0.0f;
        #pragma unroll
        for (int half = 0; half < 2; half++) {
            int c = lane + half * 32;
            float x = emb[w * C_DIM + c];
            s += x * x;
            __half h = __float2half_rn(x);
            float r = x - __half2float(h);
            g_Eh[w * C_DIM + c] = h;
            g_Er[w * C_DIM + c] = __float2half_rn(r);
        }
        #pragma unroll
        for (int o = 16; o > 0; o >>= 1) s += __shfl_xor_sync(0xffffffffu, s, o);
        if (lane == 0) {
            g_hn[w] = 0.5f * s;
            atomicMax(&g_emaxbits, fmono(s));
        }
    }
}

// ---------------------------------------------------------------------------
// STAGE 1 (R14-exact): hh scores over one K-quarter; NTILE=64, 4-stage ring,
// 1 sync/tile, precomputed B ldsm addresses. grid (128, 4), 2 CTA/SM.
__global__ void __launch_bounds__(TPB, 2) k_dist1(const float* __restrict__ z) {
    extern __shared__ char smem[];
    const uint32_t sb = smem_u32(smem);
    const int tid = threadIdx.x;
    const int lane = tid & 31;
    const int w = tid >> 5;
    const int split = blockIdx.y;
    const int ci0 = split * TPH;

    {
        int r = tid & 127;
        int half = tid >> 7;
        int t = blockIdx.x * MTILE + r;
        const float* zp = z + (size_t)(t >> 10) * (C_DIM * HW) + (t & 1023);
        float s = 0.0f;
        #pragma unroll
        for (int j = 0; j < 32; j++) {
            int c = half * 32 + j;
            float x = zp[c * HW];
            s += x * x;
            uint32_t off = sw128((uint32_t)(r * 128 + c * 2));
            *(__half*)(smem + SM1_A + off) = __float2half_rn(x);
        }
        if (split == 0) g_xn2[t * 2 + half] = s;
    }
    __syncthreads();

    u32 afr[4][4];
    {
        int arow = w * 16 + (lane & 7) + ((lane >> 3) & 1) * 8;
        int akb  = (lane >> 4) * 16;
        #pragma unroll
        for (int q = 0; q < 4; q++) {
            uint32_t addr = sb + SM1_A + sw128((uint32_t)(arow * 128 + q * 32 + akb));
            ldsm4(afr[q][0], afr[q][1], afr[q][2], afr[q][3], addr);
        }
    }

    const int brow = (lane & 7) + ((lane >> 4) & 1) * 8;
    const int bkb  = ((lane >> 3) & 1) * 16;
    const int lq   = 2 * (lane & 3);
    u32 baddr[4][4];
    #pragma unroll
    for (int q = 0; q < 4; q++)
        #pragma unroll
        for (int g2 = 0; g2 < 4; g2++)
            baddr[q][g2] = sb + SM1_B +
                sw128((uint32_t)((g2 * 16 + brow) * 128 + q * 32 + bkb));

    auto load_tile = [&](int tile, int stg) {
        const char* src = (const char*)g_Eh + (size_t)tile * (NTILE1 * C_DIM * 2);
        uint32_t dst = sb + SM1_B + (uint32_t)stg * 8192u;
        #pragma unroll
        for (int u = 0; u < 2; u++) {
            uint32_t off = (uint32_t)(u * TPB + tid) * 16u;
            cp_async16(dst + sw128(off), src + off);
        }
        if (tid < 16)
            cp_async16(sb + SM1_HN + stg * 256 + tid * 16,
                       (const char*)(g_hn + tile * NTILE1) + tid * 16);
    };

    float b1_0 = -3.4e38f, b2_0 = -3.4e38f;
    float b1_1 = -3.4e38f, b2_1 = -3.4e38f;
    int i1_0 = 0, i1_1 = 0;

    load_tile(ci0 + 0, 0); CP_COMMIT();
    load_tile(ci0 + 1, 1); CP_COMMIT();
    load_tile(ci0 + 2, 2); CP_COMMIT();

    for (int idx = 0; idx < TPH; idx++) {
        const int ci = ci0 + idx;
        const int stg = idx & 3;
        if (idx + 3 <= TPH)      { CP_WAIT(2); }
        else if (idx + 2 == TPH) { CP_WAIT(1); }
        else                     { CP_WAIT(0); }
        __syncthreads();
        if (idx + 3 < TPH) { load_tile(ci + 3, (idx + 3) & 3); CP_COMMIT(); }

        float acc[8][4];
        #pragma unroll
        for (int g = 0; g < 8; g++)
            #pragma unroll
            for (int v = 0; v < 4; v++) acc[g][v] = 0.0f;

        const uint32_t soff = (uint32_t)stg * 8192u;
        #pragma unroll
        for (int q = 0; q < 4; q++) {
            u32 bfr[8][2];
            #pragma unroll
            for (int g2 = 0; g2 < 4; g2++)
                ldsm4(bfr[2 * g2][0], bfr[2 * g2][1],
                      bfr[2 * g2 + 1][0], bfr[2 * g2 + 1][1],
                      baddr[q][g2] + soff);
            #pragma unroll
            for (int g = 0; g < 8; g++)
                mma16816(acc[g][0], acc[g][1], acc[g][2], acc[g][3],
                         afr[q][0], afr[q][1], afr[q][2], afr[q][3],
                         bfr[g][0], bfr[g][1]);
        }

        const float* hnp = (const float*)(smem + SM1_HN + stg * 256);
        const int colbase = ci * NTILE1 + lq;
        tile_top2(acc, 0, 1, hnp, lq, colbase, b1_0, b2_0, i1_0);
        tile_top2(acc, 2, 3, hnp, lq, colbase, b1_1, b2_1, i1_1);
    }

    #pragma unroll
    for (int o = 1; o <= 2; o <<= 1) {
        t2_merge_shfl(b1_0, b2_0, i1_0, o);
        t2_merge_shfl(b1_1, b2_1, i1_1, o);
    }

    if ((lane & 3) == 0) {
        int r = w * 16 + (lane >> 2);
        int tt = blockIdx.x * MTILE + r;
        g_s1b1[tt * KSPLIT1 + split] = b1_0;
        g_s1b2[tt * KSPLIT1 + split] = b2_0;
        g_s1i1[tt * KSPLIT1 + split] = i1_0;
        g_s1b1[(tt + 8) * KSPLIT1 + split] = b1_1;
        g_s1b2[(tt + 8) * KSPLIT1 + split] = b2_1;
        g_s1i1[(tt + 8) * KSPLIT1 + split] = i1_1;
    }
}

// merge stage-1 splits; adaptive certified margin from token/code norms
__global__ __launch_bounds__(256)
void k_resolve1() {
    int t = blockIdx.x * 256 + threadIdx.x;
    if (t >= N_TOK) return;
    float B1 = g_s1b1[t * KSPLIT1];
    float B2 = g_s1b2[t * KSPLIT1];
    int   I1 = g_s1i1[t * KSPLIT1];
    #pragma unroll
    for (int s = 1; s < KSPLIT1; s++) {
        float b1 = g_s1b1[t * KSPLIT1 + s];
        float b2 = g_s1b2[t * KSPLIT1 + s];
        int   i1 = g_s1i1[t * KSPLIT1 + s];
        if (b1 > B1) { B2 = fmaxf(B1, b2); B1 = b1; I1 = i1; }
        else { B2 = fmaxf(B2, b1); }
    }
    g_idx[t] = I1;
    float xn = sqrtf(g_xn2[t * 2] + g_xn2[t * 2 + 1]);
    float em = sqrtf(__uint_as_float(g_emaxbits & 0x7FFFFFFFu));
    float margin = 0.001953125f * xn * em * 1.002f + 2e-3f;
    if (B1 - B2 < margin) {
        int slot = atomicAdd(&g_nflag, 1);
        g_list[slot] = t;
    }
}

// ---------------------------------------------------------------------------
__global__ __launch_bounds__(256)
void k_pack(const float* __restrict__ z) {
    int nf = g_nflag;
    int total = nf * C_DIM;
    for (int i = blockIdx.x * 256 + threadIdx.x; i < total; i += gridDim.x * 256) {
        int li = i >> 6, c = i & 63;
        int t = g_list[li];
        float x = z[(size_t)(t >> 10) * (C_DIM * HW) + c * HW + (t & 1023)];
        __half h = __float2half_rn(x);
        g_Ph[i] = h;
        g_Pr[i] = __float2half_rn(x - __half2float(h));
    }
}

// ---------------------------------------------------------------------------
// STAGE 2: 3-term scores for flagged tokens over one K-slice (16 tiles).
__global__ void __launch_bounds__(TPB, 1) k_dist2() {
    const int nf = g_nflag;
    if ((int)blockIdx.x * MTILE >= nf) return;

    extern __shared__ char smem[];
    const uint32_t sb = smem_u32(smem);
    const int tid = threadIdx.x;
    const int lane = tid & 31;
    const int w = tid >> 5;
    const int slice = blockIdx.y;
    const int ci0 = slice * TPSLICE;
    const int ci1 = ci0 + TPSLICE;

    {
        int r = tid & 127;
        int half = tid >> 7;
        int li = blockIdx.x * MTILE + r;
        size_t rowo = (size_t)((li < nf) ? li : 0) * C_DIM;
        const uint4* srch = (const uint4*)(g_Ph + rowo);
        const uint4* srcr = (const uint4*)(g_Pr + rowo);
        #pragma unroll
        for (int j = 0; j < 4; j++) {
            int chunk = half * 4 + j;
            uint32_t off = sw128((uint32_t)(r * 128 + chunk * 16));
            *(uint4*)(smem + SM_A + off) = srch[chunk];
            *(uint4*)(smem + SM_A + 16384 + off) = srcr[chunk];
        }
    }
    __syncthreads();

    u32 afr[2][4][4];
    {
        int arow = w * 16 + (lane & 7) + ((lane >> 3) & 1) * 8;
        int akb  = (lane >> 4) * 16;
        #pragma unroll
        for (int c = 0; c < 2; c++)
            #pragma unroll
            for (int q = 0; q < 4; q++) {
                uint32_t addr = sb + SM_A + c * 16384 +
                                sw128((uint32_t)(arow * 128 + q * 32 + akb));
                ldsm4(afr[c][q][0], afr[c][q][1], afr[c][q][2], afr[c][q][3], addr);
            }
    }

    auto load_tile = [&](int tile, int bufi) {
        const char* srcs[2] = {(const char*)g_Eh, (const char*)g_Er};
        #pragma unroll
        for (int c = 0; c < 2; c++) {
            const char* src = srcs[c] + (size_t)tile * (NTILE * C_DIM * 2);
            uint32_t dst = sb + SM_B + (uint32_t)(bufi * 2 + c) * 8192u;
            #pragma unroll
            for (int u = 0; u < 2; u++) {
                uint32_t off = (uint32_t)(u * TPB + tid) * 16u;
                cp_async16(dst + sw128(off), src + off);
            }
        }
        if (tid < 16)
            cp_async16(sb + SM_HN + bufi * 256 + tid * 16,
                       (const char*)(g_hn + tile * NTILE) + tid * 16);
    };

    const int brow = (lane & 7) + ((lane >> 4) & 1) * 8;
    const int bkb  = ((lane >> 3) & 1) * 16;
    const int lq   = 2 * (lane & 3);

    float b1_0 = -3.4e38f, b2_0 = -3.4e38f;
    float b1_1 = -3.4e38f, b2_1 = -3.4e38f;
    int i1_0 = 0, i1_1 = 0;

    load_tile(ci0, 0); CP_COMMIT();
    load_tile(ci0 + 1, 1); CP_COMMIT();

    for (int ci = ci0; ci < ci1; ci++) {
        const int buf = ci & 1;
        if (ci + 1 < ci1) { CP_WAIT(1); } else { CP_WAIT(0); }
        __syncthreads();

        float acc[8][4];
        #pragma unroll
        for (int g = 0; g < 8; g++)
            #pragma unroll
            for (int v = 0; v < 4; v++) acc[g][v] = 0.0f;

        #pragma unroll
        for (int q = 0; q < 4; q++) {
            u32 bfr[8][2];
            uint32_t b0base = sb + SM_B + (uint32_t)(buf * 2) * 8192u;
            #pragma unroll
            for (int g2 = 0; g2 < 4; g2++) {
                uint32_t addr = b0base +
                    sw128((uint32_t)((g2 * 16 + brow) * 128 + q * 32 + bkb));
                ldsm4(bfr[2 * g2][0], bfr[2 * g2][1],
                      bfr[2 * g2 + 1][0], bfr[2 * g2 + 1][1], addr);
            }
            #pragma unroll
            for (int g = 0; g < 8; g++) {
                mma16816(acc[g][0], acc[g][1], acc[g][2], acc[g][3],
                         afr[0][q][0], afr[0][q][1], afr[0][q][2], afr[0][q][3],
                         bfr[g][0], bfr[g][1]);
                mma16816(acc[g][0], acc[g][1], acc[g][2], acc[g][3],
                         afr[1][q][0], afr[1][q][1], afr[1][q][2], afr[1][q][3],
                         bfr[g][0], bfr[g][1]);
            }
            uint32_t b1base = sb + SM_B + (uint32_t)(buf * 2 + 1) * 8192u;
            #pragma unroll
            for (int g2 = 0; g2 < 4; g2++) {
                uint32_t addr = b1base +
                    sw128((uint32_t)((g2 * 16 + brow) * 128 + q * 32 + bkb));
                ldsm4(bfr[2 * g2][0], bfr[2 * g2][1],
                      bfr[2 * g2 + 1][0], bfr[2 * g2 + 1][1], addr);
            }
            #pragma unroll
            for (int g = 0; g < 8; g++)
                mma16816(acc[g][0], acc[g][1], acc[g][2], acc[g][3],
                         afr[0][q][0], afr[0][q][1], afr[0][q][2], afr[0][q][3],
                         bfr[g][0], bfr[g][1]);
        }

        const float* hnp = (const float*)(smem + SM_HN + buf * 256);
        const int colbase = ci * NTILE + lq;
        tile_top2(acc, 0, 1, hnp, lq, colbase, b1_0, b2_0, i1_0);
        tile_top2(acc, 2, 3, hnp, lq, colbase, b1_1, b2_1, i1_1);

        __syncthreads();
        if (ci + 2 < ci1) { load_tile(ci + 2, buf); CP_COMMIT(); }
    }

    #pragma unroll
    for (int o = 1; o <= 2; o <<= 1) {
        t2_merge_shfl(b1_0, b2_0, i1_0, o);
        t2_merge_shfl(b1_1, b2_1, i1_1, o);
    }

    if ((lane & 3) == 0) {
        int r = w * 16 + (lane >> 2);
        #pragma unroll
        for (int pair = 0; pair < 2; pair++) {
            float pb1 = pair ? b1_1 : b1_0;
            float pb2 = pair ? b2_1 : b2_0;
            int   pi1 = pair ? i1_1 : i1_0;
            int li = blockIdx.x * MTILE + r + pair * 8;
            if (li < nf) {
                g_s2b1[li * NSLICE + slice] = pb1;
                g_s2b2[li * NSLICE + slice] = pb2;
                g_s2i1[li * NSLICE + slice] = pi1;
            }
        }
    }
}

// ---------------------------------------------------------------------------
__global__ __launch_bounds__(256)
void k_resolve2() {
    int li = blockIdx.x * 256 + threadIdx.x;
    if (li >= g_nflag) return;
    int t = g_list[li];
    float B1 = -3.4e38f, B2 = -3.4e38f;
    int I1 = 0;
    #pragma unroll
    for (int s = 0; s < NSLICE; s++) {
        float b1 = g_s2b1[li * NSLICE + s];
        float b2 = g_s2b2[li * NSLICE + s];
        int   i1 = g_s2i1[li * NSLICE + s];
        if (b1 > B1) { B2 = fmaxf(B1, b2); B1 = b1; I1 = i1; }
        else { B2 = fmaxf(B2, b1); }
    }
    g_idx[t] = I1;
    if (B1 - B2 < MARGIN2) {
        g_flag2[t] = 1;
        g_key[t] = 0xFFFFFFFFFFFFFFFFULL;
        int slot = atomicAdd(&g_nflag2, 1);
        g_list2[slot] = t;
    }
}

// ---------------------------------------------------------------------------
__global__ __launch_bounds__(256)
void k_refine(const float* __restrict__ z, const float* __restrict__ emb) {
    __shared__ float sx[C_DIM];
    __shared__ u64 rk[8];
    const int tid = threadIdx.x;
    const int lane = tid & 31;
    const int wid = tid >> 5;
    const int nf = g_nflag2;
    if (nf == 0) return;

    for (int wk = blockIdx.x; wk < nf * 64; wk += gridDim.x) {
        const int it = wk >> 6;
        const int slice = wk & 63;
        const int t = g_list2[it];
        __syncthreads();
        if (tid < C_DIM) {
            const float* zp = z + (size_t)(t >> 10) * (C_DIM * HW) + (t & 1023);
            sx[tid] = zp[tid * HW];
        }
        __syncthreads();

        u64 key = 0xFFFFFFFFFFFFFFFFULL;
        if (tid < 128) {
            int k = slice * 128 + tid;
            const float4* e4 = (const float4*)(emb + (size_t)k * C_DIM);
            float s = 0.0f;
            #pragma unroll
            for (int j = 0; j < 16; j++) {
                float4 e = e4[j];
                s += sx[4 * j] * e.x + sx[4 * j + 1] * e.y
                   + sx[4 * j + 2] * e.z + sx[4 * j + 3] * e.w;
            }
            s -= g_hn[k];
            key = ((u64)(~fmono(s)) << 32) | (u32)k;
        }
        #pragma unroll
        for (int o = 16; o > 0; o >>= 1) {
            u64 ok = __shfl_xor_sync(0xffffffffu, key, o);
            if (ok < key) key = ok;
        }
        if (lane == 0) rk[wid] = key;
        __syncthreads();
        if (tid == 0) {
            u64 kmin = rk[0];
            #pragma unroll
            for (int w2 = 1; w2 < 8; w2++) if (rk[w2] < kmin) kmin = rk[w2];
            atomicMin(&g_key[t], kmin);
        }
    }
}

// ---------------------------------------------------------------------------
// epilogue: indices, z_q, z_q_st, counts, dw  (8 threads per token)
__global__ __launch_bounds__(256)
void k_epi(const float* __restrict__ z, const float* __restrict__ emb,
           float* __restrict__ out) {
    const int gid = blockIdx.x * blockDim.x + threadIdx.x;
    const int t = gid >> 3;
    const int part = gid & 7;
    if (t >= N_TOK) return;
    const int b = t >> 10;
    const int hw = t & 1023;
    const float* zp = z + (size_t)b * (C_DIM * HW) + hw;

    int bi = g_flag2[t] ? (int)(u32)(g_key[t] & 0xFFFFFFFFULL) : g_idx[t];
    if (part == 0) {
        out[O_IDX + t] = (float)bi;
        atomicAdd(&g_counts[bi], 1.0f);
    }

    const float4* er = (const float4*)(emb + (size_t)bi * C_DIM) + part * 2;
    float* dwp = g_dw + (size_t)bi * C_DIM;
    float* zq   = out + O_ZQ   + (size_t)b * (C_DIM * HW) + hw;
    float* zqst = out + O_ZQST + (size_t)b * (C_DIM * HW) + hw;

    #pragma unroll
    for (int j = 0; j < 2; j++) {
        float4 q = er[j];
        int c = part * 8 + 4 * j;
        float x0 = zp[(c + 0) * HW];
        float x1 = zp[(c + 1) * HW];
        float x2 = zp[(c + 2) * HW];
        float x3 = zp[(c + 3) * HW];
        zq[(c + 0) * HW] = q.x;
        zq[(c + 1) * HW] = q.y;
        zq[(c + 2) * HW] = q.z;
        zq[(c + 3) * HW] = q.w;
        zqst[(c + 0) * HW] = x0 + (q.x - x0);
        zqst[(c + 1) * HW] = x1 + (q.y - x1);
        zqst[(c + 2) * HW] = x2 + (q.z - x2);
        zqst[(c + 3) * HW] = x3 + (q.w - x3);
        atomicAdd(dwp + c + 0, x0);
        atomicAdd(dwp + c + 1, x1);
        atomicAdd(dwp + c + 2, x2);
        atomicAdd(dwp + c + 3, x3);
    }
}

// ---------------------------------------------------------------------------
__global__ __launch_bounds__(256)
void k_cs(const float* __restrict__ cs, float* __restrict__ out) {
    const float OMD = 0.01f;
    int i = blockIdx.x * 256 + threadIdx.x;
    float v = 0.99f * cs[i] + OMD * g_counts[i];
    out[O_CS + i] = v;
    #pragma unroll
    for (int o = 16; o > 0; o >>= 1) v += __shfl_xor_sync(0xffffffffu, v, o);
    __shared__ float red[8];
    if ((threadIdx.x & 31) == 0) red[threadIdx.x >> 5] = v;
    __syncthreads();
    if (threadIdx.x == 0) {
        float s = red[0];
        #pragma unroll
        for (int w2 = 1; w2 < 8; w2++) s += red[w2];
        atomicAdd(&g_n, s);
    }
}

__global__ void k_emb(const float* __restrict__ cs, const float* __restrict__ avg,
                      float* __restrict__ out) {
    const float OMD = 0.01f;
    const float EPSF = 1e-5f;
    int i = blockIdx.x * blockDim.x + threadIdx.x;
    if (i >= K_CODES * C_DIM) return;
    int k = i >> 6;
    float ncs = 0.99f * cs[k] + OMD * g_counts[k];
    float navg = 0.99f * avg[i] + OMD * g_dw[i];
    float n = g_n;
    float denom = (ncs + EPSF) / (n + (float)K_CODES * EPSF) * n;
    out[O_EMB + i] = navg / denom;
    out[O_AVG + i] = navg;
}

// ---------------------------------------------------------------------------
extern "C" void kernel_launch(void* const* d_in, const int* in_sizes, int n_in,
                              void* d_out, int out_size) {
    const float* z   = (const float*)d_in[0];
    const float* emb = (const float*)d_in[1];
    const float* cs  = (const float*)d_in[2];
    const float* avg = (const float*)d_in[3];
    float* out = (float*)d_out;

    cudaFuncSetAttribute(k_dist1, cudaFuncAttributeMaxDynamicSharedMemorySize, SMEM1_TOTAL);
    cudaFuncSetAttribute(k_dist2, cudaFuncAttributeMaxDynamicSharedMemorySize, SMEM2_TOTAL);

    k_setup<<<(K_CODES * C_DIM) / 256, 256>>>(emb);                        // 1
    k_dist1<<<dim3(N_TOK / MTILE, KSPLIT1), TPB, SMEM1_TOTAL>>>(z);        // 2
    k_resolve1<<<N_TOK / 256, 256>>>();                                    // 3
    k_pack<<<256, 256>>>(z);                                               // 4
    k_dist2<<<dim3(N_TOK / MTILE, NSLICE), TPB, SMEM2_TOTAL>>>();          // 5
    k_resolve2<<<N_TOK / 256, 256>>>();                                    // 6
    k_refine<<<128, 256>>>(z, emb);                                        // 7
    k_epi<<<(8 * N_TOK + 255) / 256, 256>>>(z, emb, out);                  // 8
    k_cs<<<K_CODES / 256, 256>>>(cs, out);                                 // 9
    k_emb<<<(K_CODES * C_DIM + 255) / 256, 256>>>(cs, avg, out);           // 10
}